// round 16
// baseline (speedup 1.0000x reference)
#include <cuda_runtime.h>
#include <math.h>
#include <stdint.h>

// Fused TreeLSTM cell, tf32 mma.sync (m16n8k8), 512 threads / 16 warps.
// CTA = 64 rows; chunk = 64k x 128c (32KB), double-buffered -> 30 sync phases.
// Warp (rw, cq): rows rw*16..+15, cols cq*32..+31. A and B fragment-packed
// in smem (uint4 granules, XOR swizzle).

#define THREADS 512
#define TM 64
#define B_WORDS 8192                       // one 64k x 128c chunk (32KB)
#define OFF_B (TM * 384)                   // packed A = 24576 words (96KB)
#define OFF_P (OFF_B + 2 * B_WORDS)        // 40960 (64 rows x 4 partials)
#define SMEM_WORDS (OFF_P + 256)
#define SMEM_BYTES (SMEM_WORDS * 4)        // 164864

__device__ __forceinline__ uint32_t tf32r(float x) {
    uint32_t r; asm("cvt.rna.tf32.f32 %0, %1;" : "=r"(r) : "f"(x)); return r;
}
__device__ __forceinline__ void mma8(float d[4], uint32_t a0, uint32_t a1,
                                     uint32_t a2, uint32_t a3,
                                     uint32_t b0, uint32_t b1)
{
    asm volatile(
        "mma.sync.aligned.m16n8k8.row.col.f32.tf32.tf32.f32 "
        "{%0,%1,%2,%3}, {%4,%5,%6,%7}, {%8,%9}, {%0,%1,%2,%3};"
        : "+f"(d[0]), "+f"(d[1]), "+f"(d[2]), "+f"(d[3])
        : "r"(a0), "r"(a1), "r"(a2), "r"(a3), "r"(b0), "r"(b1));
}
__device__ __forceinline__ float sigm(float x) { return 1.f / (1.f + expf(-x)); }
__device__ __forceinline__ void quadred(float& v)
{
    v += __shfl_xor_sync(0xffffffffu, v, 1);
    v += __shfl_xor_sync(0xffffffffu, v, 2);
}

// ---- packed-A store: A u4 index = k8*128 + rg*64 + (l*2+m) ^ f(k8&3) ----
__device__ __forceinline__ void storeA(uint32_t* sA, int r, int k, float v)
{
    int rg = r >> 5, m = (r >> 4) & 1, hi = (r >> 3) & 1, g = r & 7;
    int k8 = k >> 3, kof = (k >> 2) & 1, t4 = k & 3;
    int l = g * 4 + t4;
    uint32_t u4 = (uint32_t)(k8 * 128 + rg * 64 + l * 2 + m)
                ^ (uint32_t)((g ^ (2 * (k8 & 3))) & 7);
    sA[u4 * 4 + kof * 2 + hi] = tf32r(v);
}

// Weight chunk load: thread owns row c_ (0..127), two k8-slots {ks, ks+4}.
__device__ __forceinline__ void load_chunk(float4 wv[4], const float* __restrict__ Wg,
                                           const float* __restrict__ Ug,
                                           int ch, int c_, int ks2)
{
#pragma unroll
    for (int s = 0; s < 2; s++) {
        int k8s = ks2 + s * 4;
        int kg = ch * 64 + k8s * 8;
        const float* src = (kg < 128) ? Wg + (size_t)c_ * 128 + kg
                                      : Ug + (size_t)c_ * 256 + (kg - 128);
        wv[s * 2 + 0] = __ldg((const float4*)src);
        wv[s * 2 + 1] = __ldg((const float4*)(src + 4));
    }
}

// ---- packed-B stage: u4 = cq*512 + k8s*64 + ((l*2 + n8h) ^ f(k8s&3)) ----
__device__ __forceinline__ void stageB(uint32_t* bb, const float4 wv[4],
                                       int c_, int ks2)
{
    int cq = c_ >> 5, n8h = (c_ >> 4) & 1, n8l = (c_ >> 3) & 1, g = c_ & 7;
#pragma unroll
    for (int s = 0; s < 2; s++) {
        int k8s = ks2 + s * 4;
        uint32_t fw = (uint32_t)((g ^ (2 * (k8s & 3))) & 7);
        uint32_t u4b = (uint32_t)(cq * 512 + k8s * 64 + n8h);
        const float* w0 = (const float*)&wv[s * 2 + 0];
        const float* w1 = (const float*)&wv[s * 2 + 1];
#pragma unroll
        for (int t4e = 0; t4e < 4; t4e++) {
            uint32_t u4s = ((uint32_t)(g * 4 + t4e) * 2 + u4b) ^ fw;
            // careful: XOR applies to low bits only; (l*2+n8h) < 64, fw < 8
            u4s = (uint32_t)(cq * 512 + k8s * 64)
                + (((uint32_t)(g * 4 + t4e) * 2 + (uint32_t)n8h) ^ fw);
            uint2 pr = { tf32r(w0[t4e]), tf32r(w1[t4e]) };
            *(uint2*)((char*)bb + u4s * 16 + n8l * 8) = pr;
        }
    }
}

// GEMM chunks [ch0, ch1): acc += A[16 rows] @ [Wg|Ug]^T[32 cols].
__device__ void run_gate(float acc[4][4], const float* __restrict__ Wg,
                         const float* __restrict__ Ug,
                         const char* sAp, char* sBp, int& gc,
                         int ch0, int ch1, int c_, int ks2,
                         int rw, int cq, int lane)
{
    // per-(k8&3) swizzled offsets (bytes), applied with k8l*2048 / k8l*1024
    uint32_t apre[4], bpre0[4], bpre1[4];
#pragma unroll
    for (int j = 0; j < 4; j++) {
        uint32_t f = (uint32_t)(((lane >> 2) ^ (2 * j)) & 7);
        apre[j] = (uint32_t)((rw >> 1) * 64 + ((lane * 2 + (rw & 1)) ^ f)) * 16;
        bpre0[j] = (uint32_t)((lane * 2 + 0) ^ f) * 16;
        bpre1[j] = (uint32_t)((lane * 2 + 1) ^ f) * 16;
    }

    float4 wv[4];
    load_chunk(wv, Wg, Ug, ch0, c_, ks2);

    for (int ch = ch0; ch < ch1; ch++) {
        char* bb = sBp + ((gc & 1) ? 32768 : 0);
        gc++;
        stageB((uint32_t*)bb, wv, c_, ks2);
        __syncthreads();
        if (ch + 1 < ch1) load_chunk(wv, Wg, Ug, ch + 1, c_, ks2);
        const char* pA = sAp + ch * 16384;
        const char* pB = bb + cq * 8192;
#pragma unroll
        for (int k8l = 0; k8l < 8; k8l++) {
            uint4 aa = *(const uint4*)(pA + k8l * 2048 + apre[k8l & 3]);
            uint4 b0 = *(const uint4*)(pB + k8l * 1024 + bpre0[k8l & 3]);
            uint4 b1 = *(const uint4*)(pB + k8l * 1024 + bpre1[k8l & 3]);
            mma8(acc[0], aa.x, aa.y, aa.z, aa.w, b0.x, b0.y);
            mma8(acc[1], aa.x, aa.y, aa.z, aa.w, b0.z, b0.w);
            mma8(acc[2], aa.x, aa.y, aa.z, aa.w, b1.x, b1.y);
            mma8(acc[3], aa.x, aa.y, aa.z, aa.w, b1.z, b1.w);
        }
        // single sync/chunk: buffer staged next iter was last read two
        // iterations ago, past this iteration's sync for every thread.
    }
}

// LayerNorm over 128-col rows split across 4 col-quarter warps; lane holds
// 2 rows x 8 cols. sP[64 rows][4 partials]; 3 CTA barriers.
__device__ void ln2(float xx[2][8], float* sP, const int rl[2], int cq, int t4,
                    const float* __restrict__ gamma,
                    const float* __restrict__ beta, int cb)
{
    float s[2];
#pragma unroll
    for (int i = 0; i < 2; i++) {
        float v = 0.f;
#pragma unroll
        for (int j = 0; j < 8; j++) v += xx[i][j];
        quadred(v);
        s[i] = v;
    }
    if (t4 == 0)
#pragma unroll
        for (int i = 0; i < 2; i++) sP[rl[i] * 4 + cq] = s[i];
    __syncthreads();
    float mu[2];
#pragma unroll
    for (int i = 0; i < 2; i++)
        mu[i] = (sP[rl[i] * 4] + sP[rl[i] * 4 + 1]
               + sP[rl[i] * 4 + 2] + sP[rl[i] * 4 + 3]) * 0.0078125f;
    __syncthreads();
    float q[2];
#pragma unroll
    for (int i = 0; i < 2; i++) {
        float v = 0.f;
#pragma unroll
        for (int j = 0; j < 8; j++) {
            xx[i][j] -= mu[i];
            v += xx[i][j] * xx[i][j];
        }
        quadred(v);
        q[i] = v;
    }
    if (t4 == 0)
#pragma unroll
        for (int i = 0; i < 2; i++) sP[rl[i] * 4 + cq] = q[i];
    __syncthreads();
#pragma unroll
    for (int i = 0; i < 2; i++) {
        float rs = rsqrtf((sP[rl[i] * 4] + sP[rl[i] * 4 + 1]
                         + sP[rl[i] * 4 + 2] + sP[rl[i] * 4 + 3])
                          * 0.0078125f + 1e-5f);
#pragma unroll
        for (int n8 = 0; n8 < 4; n8++) {
            float2 gv = __ldg((const float2*)(gamma + cb + n8 * 8));
            float2 bv = __ldg((const float2*)(beta  + cb + n8 * 8));
            xx[i][2 * n8]     = xx[i][2 * n8]     * rs * gv.x + bv.x;
            xx[i][2 * n8 + 1] = xx[i][2 * n8 + 1] * rs * gv.y + bv.y;
        }
    }
    __syncthreads();   // protect sP before next gate's staging reuse
}

__global__ __launch_bounds__(THREADS, 1) void treelstm_mma(
    const float* __restrict__ emb,  const float* __restrict__ h_child,
    const float* __restrict__ c_child, const int* __restrict__ n_type,
    const float* __restrict__ W_iou, const float* __restrict__ U_iou,
    const float* __restrict__ b_iou, const float* __restrict__ W_f,
    const float* __restrict__ U_f,   const float* __restrict__ b_f,
    const float* __restrict__ g_i,  const float* __restrict__ b_i,
    const float* __restrict__ g_o,  const float* __restrict__ b_o,
    const float* __restrict__ g_u,  const float* __restrict__ b_u,
    const float* __restrict__ gn_f, const float* __restrict__ bn_f,
    const float* __restrict__ gn_c, const float* __restrict__ bn_c,
    float* __restrict__ out, int n)
{
    extern __shared__ uint32_t sm[];
    uint32_t* sA = sm;
    char*     sAp = (char*)sm;
    char*     sBp = (char*)(sm + OFF_B);
    float*    sP = (float*)(sm + OFF_P);

    const int tid = threadIdx.x;
    const int lane = tid & 31, warp = tid >> 5;
    const int t4 = lane & 3, g = lane >> 2;
    const int rw = warp & 3, cq = warp >> 2;
    const int cb = cq * 32 + t4 * 2;
    const int c_ = tid & 127, ks2 = tid >> 7;    // staging: row, k8-slot pair
    const int row0 = blockIdx.x * TM;
    const int rl[2] = { rw * 16 + g, rw * 16 + g + 8 };

    // ---- Phase 0: pack A = [emb | ht0 | ht1] into fragment layout ----
    for (int e = tid; e < TM * 32; e += THREADS) {
        int r = e >> 5, k4 = (e & 31) * 4;
        float4 v = __ldg((const float4*)(emb + (size_t)(row0 + r) * 128 + k4));
        storeA(sA, r, k4 + 0, v.x);
        storeA(sA, r, k4 + 1, v.y);
        storeA(sA, r, k4 + 2, v.z);
        storeA(sA, r, k4 + 3, v.w);
    }
    for (int e = tid; e < TM * 128; e += THREADS) {
        int r = e >> 7, c = e & 127;
        const float* hp = h_child + ((size_t)(row0 + r) * 4) * 128 + c;
        float h0 = 0.f, h1 = 0.f;
#pragma unroll
        for (int k = 0; k < 4; k++) {
            float v = __ldg(hp + k * 128);
            if (__ldg(n_type + (size_t)(row0 + r) * 4 + k) == 0) h0 += v; else h1 += v;
        }
        storeA(sA, r, 128 + c, h0);
        storeA(sA, r, 256 + c, h1);
    }
    __syncthreads();

    float acc[4][4], cS[2][8], xx[2][8];
    int gc = 0;

#define ZACC()                                                \
    _Pragma("unroll") for (int n8 = 0; n8 < 4; n8++)          \
    _Pragma("unroll") for (int q = 0; q < 4; q++) acc[n8][q] = 0.f;

#define GATHER(BIAS)                                                   \
    _Pragma("unroll") for (int n8 = 0; n8 < 4; n8++) {                 \
        float2 bv = __ldg((const float2*)((BIAS) + cb + n8 * 8));      \
        xx[0][2*n8]   = acc[n8][0] + bv.x;                             \
        xx[0][2*n8+1] = acc[n8][1] + bv.y;                             \
        xx[1][2*n8]   = acc[n8][2] + bv.x;                             \
        xx[1][2*n8+1] = acc[n8][3] + bv.y;                             \
    }

    // ---- Gate u: cS = tanh(LN(u)) ----
    ZACC();
    run_gate(acc, W_iou + 256 * 128, U_iou + 256 * 256, sAp, sBp, gc, 0, 6,
             c_, ks2, rw, cq, lane);
    GATHER(b_iou + 256);
    ln2(xx, sP, rl, cq, t4, g_u, b_u, cb);
#pragma unroll
    for (int i = 0; i < 2; i++)
#pragma unroll
        for (int j = 0; j < 8; j++) cS[i][j] = tanhf(xx[i][j]);

    // ---- Gate i: cS *= sigm(LN(i)) ----
    ZACC();
    run_gate(acc, W_iou, U_iou, sAp, sBp, gc, 0, 6, c_, ks2, rw, cq, lane);
    GATHER(b_iou);
    ln2(xx, sP, rl, cq, t4, g_i, b_i, cb);
#pragma unroll
    for (int i = 0; i < 2; i++)
#pragma unroll
        for (int j = 0; j < 8; j++) cS[i][j] *= sigm(xx[i][j]);

    // ---- Gates f0 / f1: cS += sigm(LN(f)) * ct ----
#pragma unroll 1
    for (int ft = 0; ft < 2; ft++) {
        ZACC();
        run_gate(acc, W_f, U_f + ft * 128 * 256, sAp, sBp, gc, 0, 6,
                 c_, ks2, rw, cq, lane);
        GATHER(b_f);
        ln2(xx, sP, rl, cq, t4, gn_f, bn_f, cb);
#pragma unroll
        for (int i = 0; i < 2; i++) {
            size_t grow = (size_t)(row0 + rl[i]);
            int4 nt = __ldg((const int4*)(n_type + grow * 4));
            int ntk[4] = { nt.x, nt.y, nt.z, nt.w };
            float ct[8] = { 0.f, 0.f, 0.f, 0.f, 0.f, 0.f, 0.f, 0.f };
#pragma unroll
            for (int k = 0; k < 4; k++) {
                if (ntk[k] == ft) {
                    const float* cp = c_child + grow * 512 + k * 128 + cb;
#pragma unroll
                    for (int n8 = 0; n8 < 4; n8++) {
                        float2 v = __ldg((const float2*)(cp + n8 * 8));
                        ct[2 * n8] += v.x; ct[2 * n8 + 1] += v.y;
                    }
                }
            }
#pragma unroll
            for (int j = 0; j < 8; j++) cS[i][j] += sigm(xx[i][j]) * ct[j];
        }
    }

    // ---- write c; cS := tanh(LN(c)) ----
#pragma unroll
    for (int i = 0; i < 2; i++) {
        float* oc = out + (size_t)n * 128 + (size_t)(row0 + rl[i]) * 128 + cb;
#pragma unroll
        for (int n8 = 0; n8 < 4; n8++) {
            *(float2*)(oc + n8 * 8) = make_float2(cS[i][2*n8], cS[i][2*n8+1]);
            xx[i][2*n8] = cS[i][2*n8]; xx[i][2*n8+1] = cS[i][2*n8+1];
        }
    }
    ln2(xx, sP, rl, cq, t4, gn_c, bn_c, cb);
#pragma unroll
    for (int i = 0; i < 2; i++)
#pragma unroll
        for (int j = 0; j < 8; j++) cS[i][j] = tanhf(xx[i][j]);

    // ---- Gate o: h = sigm(LN(o)) * tanh(LN(c)) ----
    ZACC();
    run_gate(acc, W_iou + 128 * 128, U_iou + 128 * 256, sAp, sBp, gc, 0, 6,
             c_, ks2, rw, cq, lane);
    GATHER(b_iou + 128);
    ln2(xx, sP, rl, cq, t4, g_o, b_o, cb);
#pragma unroll
    for (int i = 0; i < 2; i++) {
        float* oh = out + (size_t)(row0 + rl[i]) * 128 + cb;
#pragma unroll
        for (int n8 = 0; n8 < 4; n8++)
            *(float2*)(oh + n8 * 8) = make_float2(sigm(xx[i][2*n8])   * cS[i][2*n8],
                                                  sigm(xx[i][2*n8+1]) * cS[i][2*n8+1]);
    }
#undef GATHER
#undef ZACC
}

extern "C" void kernel_launch(void* const* d_in, const int* in_sizes, int n_in,
                              void* d_out, int out_size)
{
    const float* emb     = (const float*)d_in[0];
    const float* h_child = (const float*)d_in[1];
    const float* c_child = (const float*)d_in[2];
    const int*   n_type  = (const int*)  d_in[3];
    const float* W_iou   = (const float*)d_in[4];
    const float* U_iou   = (const float*)d_in[5];
    const float* b_iou   = (const float*)d_in[6];
    const float* W_f     = (const float*)d_in[7];
    const float* U_f     = (const float*)d_in[8];
    const float* b_f     = (const float*)d_in[9];
    const float* g_i  = (const float*)d_in[10];
    const float* b_i  = (const float*)d_in[11];
    const float* g_o  = (const float*)d_in[12];
    const float* b_o  = (const float*)d_in[13];
    const float* g_u  = (const float*)d_in[14];
    const float* b_u  = (const float*)d_in[15];
    const float* gn_f = (const float*)d_in[16];
    const float* bn_f = (const float*)d_in[17];
    const float* gn_c = (const float*)d_in[18];
    const float* bn_c = (const float*)d_in[19];
    float* out = (float*)d_out;

    int n = in_sizes[0] / 128;

    static int smem_set = 0;
    if (!smem_set) {
        cudaFuncSetAttribute(treelstm_mma,
                             cudaFuncAttributeMaxDynamicSharedMemorySize,
                             SMEM_BYTES);
        smem_set = 1;
    }

    treelstm_mma<<<n / TM, THREADS, SMEM_BYTES>>>(
        emb, h_child, c_child, n_type, W_iou, U_iou, b_iou, W_f, U_f, b_f,
        g_i, b_i, g_o, b_o, g_u, b_u, gn_f, bn_f, gn_c, bn_c, out, n);
}

// round 17
// speedup vs baseline: 1.6453x; 1.6453x over previous
#include <cuda_runtime.h>
#include <math.h>
#include <stdint.h>

// Fused TreeLSTM cell, tf32 mma.sync (m16n8k8), 512 threads / 16 warps.
// CTA = 128 rows. Warp (rg, cq): rows rg*32..+31, cols cq*32..+31.
// A: natural layout + word XOR swizzle. B: cp.async (LDGSTS) double-buffered
// staging in natural layout + 16B-granule XOR swizzle -> staging latency is
// overlapped with MMA consume instead of serialized before it.

#define THREADS 512
#define AS 384
#define B_WORDS 4096                       // one 32k x 128c chunk (16KB)
#define OFF_B (128 * AS)                   // 49152 words
#define OFF_P (OFF_B + 2 * B_WORDS)        // 57344 (128 rows x 4 partials)
#define SMEM_WORDS (OFF_P + 512)
#define SMEM_BYTES (SMEM_WORDS * 4)        // 231424 <= 232448

__device__ __forceinline__ uint32_t tf32r(float x) {
    uint32_t r; asm("cvt.rna.tf32.f32 %0, %1;" : "=r"(r) : "f"(x)); return r;
}
__device__ __forceinline__ void mma8(float d[4], uint32_t a0, uint32_t a1,
                                     uint32_t a2, uint32_t a3,
                                     uint32_t b0, uint32_t b1)
{
    asm volatile(
        "mma.sync.aligned.m16n8k8.row.col.f32.tf32.tf32.f32 "
        "{%0,%1,%2,%3}, {%4,%5,%6,%7}, {%8,%9}, {%0,%1,%2,%3};"
        : "+f"(d[0]), "+f"(d[1]), "+f"(d[2]), "+f"(d[3])
        : "r"(a0), "r"(a1), "r"(a2), "r"(a3), "r"(b0), "r"(b1));
}
__device__ __forceinline__ float sigm(float x) { return 1.f / (1.f + expf(-x)); }
__device__ __forceinline__ void quadred(float& v)
{
    v += __shfl_xor_sync(0xffffffffu, v, 1);
    v += __shfl_xor_sync(0xffffffffu, v, 2);
}
__device__ __forceinline__ void cp16(uint32_t dst, const void* src)
{
    asm volatile("cp.async.ca.shared.global [%0], [%1], 16;"
                 :: "r"(dst), "l"(src) : "memory");
}
#define CP_COMMIT() asm volatile("cp.async.commit_group;" ::: "memory")
#define CP_WAIT0()  asm volatile("cp.async.wait_group 0;" ::: "memory")

// Issue one 32k x 128c weight chunk via cp.async into buffer at sb_addr.
// Thread: row c_ (0..127), granule pair gp (0..3) -> granules 2gp, 2gp+1.
// Dest granule swizzle: g8 -> g8 ^ (c_ & 7) keeps consumer reads conflict-free.
__device__ __forceinline__ void stage_issue(
    uint32_t sb_addr, const float* __restrict__ Wg, const float* __restrict__ Ug,
    int ch, int c_, int gp)
{
#pragma unroll
    for (int s = 0; s < 2; s++) {
        int g8 = gp * 2 + s;
        int kg = ch * 32 + g8 * 4;
        const float* src = (kg < 128) ? Wg + (size_t)c_ * 128 + kg
                                      : Ug + (size_t)c_ * 256 + (kg - 128);
        uint32_t dw = (uint32_t)(c_ * 32 + ((g8 ^ (c_ & 7)) * 4));
        cp16(sb_addr + dw * 4, src);
    }
    CP_COMMIT();
}

// One gate GEMM: acc += A[32 rows] @ [Wg|Ug]^T[32 cols], 12 chunks of 32k.
__device__ void run_gate(float acc[2][4][4], const float* __restrict__ Wg,
                         const float* __restrict__ Ug,
                         const uint32_t* sA, const uint32_t* sBw,
                         uint32_t sb_base, int& gc,
                         int c_, int gp, int rg, int cq, int lane)
{
    const int t4 = lane & 3, g = lane >> 2, g4 = g * 4;
    const int r0 = rg * 32 + g;
    const uint32_t* aR0 = sA + (size_t)(r0     ) * AS;
    const uint32_t* aR1 = sA + (size_t)(r0 + 8 ) * AS;
    const uint32_t* aR2 = sA + (size_t)(r0 + 16) * AS;
    const uint32_t* aR3 = sA + (size_t)(r0 + 24) * AS;
    uint32_t brb[4];
#pragma unroll
    for (int n8 = 0; n8 < 4; n8++)
        brb[n8] = (uint32_t)((cq * 32 + n8 * 8 + g) * 32 + t4);

    // prologue: issue chunk 0 (target buffer last consumed 2 chunks ago; all
    // threads are past the intervening LN barriers, so no read hazard)
    stage_issue(sb_base + ((gc & 1) ? B_WORDS * 4 : 0), Wg, Ug, 0, c_, gp);

    for (int ch = 0; ch < 12; ch++) {
        CP_WAIT0();          // this thread's copies for chunk ch done
        __syncthreads();     // all threads' copies visible; prev buffer free
        if (ch + 1 < 12)
            stage_issue(sb_base + (((gc + 1) & 1) ? B_WORDS * 4 : 0),
                        Wg, Ug, ch + 1, c_, gp);
        const uint32_t* bb = sBw + ((gc & 1) ? B_WORDS : 0);
        const int cb32 = ch * 32;
#pragma unroll
        for (int k8 = 0; k8 < 4; k8++) {
            int w0 = cb32 + ((k8 * 8 + t4) ^ g4);
            int w1 = cb32 + ((k8 * 8 + t4 + 4) ^ g4);
            uint32_t a00 = aR0[w0], a01 = aR1[w0], a02 = aR0[w1], a03 = aR1[w1];
            uint32_t a10 = aR2[w0], a11 = aR3[w0], a12 = aR2[w1], a13 = aR3[w1];
            uint32_t x0 = (uint32_t)(((2 * k8) ^ g) * 4);
            uint32_t x1 = (uint32_t)(((2 * k8 + 1) ^ g) * 4);
#pragma unroll
            for (int n8 = 0; n8 < 4; n8++) {
                uint32_t b0 = bb[brb[n8] + x0];
                uint32_t b1 = bb[brb[n8] + x1];
                mma8(acc[0][n8], a00, a01, a02, a03, b0, b1);
                mma8(acc[1][n8], a10, a11, a12, a13, b0, b1);
            }
        }
        gc++;
    }
}

// LayerNorm over 128-col rows split across 4 col-quarter warps; lane holds
// 4 rows x 8 cols. sP[128 rows][4 partials]; 4 CTA barriers.
__device__ void ln4(float xx[4][8], float* sP, const int rl[4], int cq, int t4,
                    const float* __restrict__ gamma,
                    const float* __restrict__ beta, int cb)
{
    float s[4];
#pragma unroll
    for (int i = 0; i < 4; i++) {
        float v = 0.f;
#pragma unroll
        for (int j = 0; j < 8; j++) v += xx[i][j];
        quadred(v);
        s[i] = v;
    }
    if (t4 == 0)
#pragma unroll
        for (int i = 0; i < 4; i++) sP[rl[i] * 4 + cq] = s[i];
    __syncthreads();
    float mu[4];
#pragma unroll
    for (int i = 0; i < 4; i++)
        mu[i] = (sP[rl[i] * 4] + sP[rl[i] * 4 + 1]
               + sP[rl[i] * 4 + 2] + sP[rl[i] * 4 + 3]) * 0.0078125f;
    __syncthreads();
    float q[4];
#pragma unroll
    for (int i = 0; i < 4; i++) {
        float v = 0.f;
#pragma unroll
        for (int j = 0; j < 8; j++) {
            xx[i][j] -= mu[i];
            v += xx[i][j] * xx[i][j];
        }
        quadred(v);
        q[i] = v;
    }
    if (t4 == 0)
#pragma unroll
        for (int i = 0; i < 4; i++) sP[rl[i] * 4 + cq] = q[i];
    __syncthreads();
#pragma unroll
    for (int i = 0; i < 4; i++) {
        float rs = rsqrtf((sP[rl[i] * 4] + sP[rl[i] * 4 + 1]
                         + sP[rl[i] * 4 + 2] + sP[rl[i] * 4 + 3])
                          * 0.0078125f + 1e-5f);
#pragma unroll
        for (int n8 = 0; n8 < 4; n8++) {
            float2 gv = __ldg((const float2*)(gamma + cb + n8 * 8));
            float2 bv = __ldg((const float2*)(beta  + cb + n8 * 8));
            xx[i][2 * n8]     = xx[i][2 * n8]     * rs * gv.x + bv.x;
            xx[i][2 * n8 + 1] = xx[i][2 * n8 + 1] * rs * gv.y + bv.y;
        }
    }
    __syncthreads();   // protect sP against the next LN's writes
}

__global__ __launch_bounds__(THREADS, 1) void treelstm_mma(
    const float* __restrict__ emb,  const float* __restrict__ h_child,
    const float* __restrict__ c_child, const int* __restrict__ n_type,
    const float* __restrict__ W_iou, const float* __restrict__ U_iou,
    const float* __restrict__ b_iou, const float* __restrict__ W_f,
    const float* __restrict__ U_f,   const float* __restrict__ b_f,
    const float* __restrict__ g_i,  const float* __restrict__ b_i,
    const float* __restrict__ g_o,  const float* __restrict__ b_o,
    const float* __restrict__ g_u,  const float* __restrict__ b_u,
    const float* __restrict__ gn_f, const float* __restrict__ bn_f,
    const float* __restrict__ gn_c, const float* __restrict__ bn_c,
    float* __restrict__ out, int n)
{
    extern __shared__ uint32_t sm[];
    uint32_t* sA  = sm;
    uint32_t* sBw = sm + OFF_B;
    float*    sP  = (float*)(sm + OFF_P);
    const uint32_t sb_base = (uint32_t)__cvta_generic_to_shared(sBw);

    const int tid = threadIdx.x;
    const int lane = tid & 31, warp = tid >> 5;
    const int t4 = lane & 3, g = lane >> 2;
    const int rg = warp & 3, cq = warp >> 2;
    const int cb = cq * 32 + t4 * 2;
    const int c_ = tid >> 2, gp = tid & 3;       // staging coords
    const int row0 = blockIdx.x * 128;
    const int rl[4] = { rg * 32 + g, rg * 32 + g + 8,
                        rg * 32 + g + 16, rg * 32 + g + 24 };

    // ---- Phase 0: A = [emb | ht0 | ht1] as tf32, word-XOR swizzled ----
    for (int e = tid; e < 128 * 32; e += THREADS) {
        int r = e >> 5, k4 = (e & 31) * 4;
        int sw = (r & 7) * 4;
        float4 v = __ldg((const float4*)(emb + (size_t)(row0 + r) * 128 + k4));
        uint32_t* dr = sA + (size_t)r * AS;
        dr[(k4 + 0) ^ sw] = tf32r(v.x);
        dr[(k4 + 1) ^ sw] = tf32r(v.y);
        dr[(k4 + 2) ^ sw] = tf32r(v.z);
        dr[(k4 + 3) ^ sw] = tf32r(v.w);
    }
    for (int e = tid; e < 128 * 128; e += THREADS) {
        int r = e >> 7, c = e & 127;
        int sw = (r & 7) * 4;
        const float* hp = h_child + ((size_t)(row0 + r) * 4) * 128 + c;
        float h0 = 0.f, h1 = 0.f;
#pragma unroll
        for (int k = 0; k < 4; k++) {
            float v = __ldg(hp + k * 128);
            if (__ldg(n_type + (size_t)(row0 + r) * 4 + k) == 0) h0 += v; else h1 += v;
        }
        uint32_t* dr = sA + (size_t)r * AS;
        dr[(128 + c) ^ sw] = tf32r(h0);
        dr[(256 + c) ^ sw] = tf32r(h1);
    }
    __syncthreads();

    float acc[2][4][4], cS[4][8], xx[4][8];
    int gc = 0;

#define ZACC()                                                \
    _Pragma("unroll") for (int m = 0; m < 2; m++)             \
    _Pragma("unroll") for (int n8 = 0; n8 < 4; n8++)          \
    _Pragma("unroll") for (int q = 0; q < 4; q++) acc[m][n8][q] = 0.f;

#define GATHER(BIAS)                                                   \
    _Pragma("unroll") for (int n8 = 0; n8 < 4; n8++) {                 \
        float2 bv = __ldg((const float2*)((BIAS) + cb + n8 * 8));      \
        xx[0][2*n8]   = acc[0][n8][0] + bv.x;                          \
        xx[0][2*n8+1] = acc[0][n8][1] + bv.y;                          \
        xx[1][2*n8]   = acc[0][n8][2] + bv.x;                          \
        xx[1][2*n8+1] = acc[0][n8][3] + bv.y;                          \
        xx[2][2*n8]   = acc[1][n8][0] + bv.x;                          \
        xx[2][2*n8+1] = acc[1][n8][1] + bv.y;                          \
        xx[3][2*n8]   = acc[1][n8][2] + bv.x;                          \
        xx[3][2*n8+1] = acc[1][n8][3] + bv.y;                          \
    }

    // ---- Gate u: cS = tanh(LN(u)) ----
    ZACC();
    run_gate(acc, W_iou + 256 * 128, U_iou + 256 * 256, sA, sBw, sb_base, gc,
             c_, gp, rg, cq, lane);
    GATHER(b_iou + 256);
    ln4(xx, sP, rl, cq, t4, g_u, b_u, cb);
#pragma unroll
    for (int i = 0; i < 4; i++)
#pragma unroll
        for (int j = 0; j < 8; j++) cS[i][j] = tanhf(xx[i][j]);

    // ---- Gate i: cS *= sigm(LN(i)) ----
    ZACC();
    run_gate(acc, W_iou, U_iou, sA, sBw, sb_base, gc, c_, gp, rg, cq, lane);
    GATHER(b_iou);
    ln4(xx, sP, rl, cq, t4, g_i, b_i, cb);
#pragma unroll
    for (int i = 0; i < 4; i++)
#pragma unroll
        for (int j = 0; j < 8; j++) cS[i][j] *= sigm(xx[i][j]);

    // ---- Gates f0 / f1: cS += sigm(LN(f)) * ct ----
#pragma unroll 1
    for (int ft = 0; ft < 2; ft++) {
        ZACC();
        run_gate(acc, W_f, U_f + ft * 128 * 256, sA, sBw, sb_base, gc,
                 c_, gp, rg, cq, lane);
        GATHER(b_f);
        ln4(xx, sP, rl, cq, t4, gn_f, bn_f, cb);
#pragma unroll
        for (int i = 0; i < 4; i++) {
            size_t grow = (size_t)(row0 + rl[i]);
            int4 nt = __ldg((const int4*)(n_type + grow * 4));
            int ntk[4] = { nt.x, nt.y, nt.z, nt.w };
            float ct[8] = { 0.f, 0.f, 0.f, 0.f, 0.f, 0.f, 0.f, 0.f };
#pragma unroll
            for (int k = 0; k < 4; k++) {
                if (ntk[k] == ft) {
                    const float* cp = c_child + grow * 512 + k * 128 + cb;
#pragma unroll
                    for (int n8 = 0; n8 < 4; n8++) {
                        float2 v = __ldg((const float2*)(cp + n8 * 8));
                        ct[2 * n8] += v.x; ct[2 * n8 + 1] += v.y;
                    }
                }
            }
#pragma unroll
            for (int j = 0; j < 8; j++) cS[i][j] += sigm(xx[i][j]) * ct[j];
        }
    }

    // ---- write c; cS := tanh(LN(c)) ----
#pragma unroll
    for (int i = 0; i < 4; i++) {
        float* oc = out + (size_t)n * 128 + (size_t)(row0 + rl[i]) * 128 + cb;
#pragma unroll
        for (int n8 = 0; n8 < 4; n8++) {
            *(float2*)(oc + n8 * 8) = make_float2(cS[i][2*n8], cS[i][2*n8+1]);
            xx[i][2*n8] = cS[i][2*n8]; xx[i][2*n8+1] = cS[i][2*n8+1];
        }
    }
    ln4(xx, sP, rl, cq, t4, gn_c, bn_c, cb);
#pragma unroll
    for (int i = 0; i < 4; i++)
#pragma unroll
        for (int j = 0; j < 8; j++) cS[i][j] = tanhf(xx[i][j]);

    // ---- Gate o: h = sigm(LN(o)) * tanh(LN(c)) ----
    ZACC();
    run_gate(acc, W_iou + 128 * 128, U_iou + 128 * 256, sA, sBw, sb_base, gc,
             c_, gp, rg, cq, lane);
    GATHER(b_iou + 128);
    ln4(xx, sP, rl, cq, t4, g_o, b_o, cb);
#pragma unroll
    for (int i = 0; i < 4; i++) {
        float* oh = out + (size_t)(row0 + rl[i]) * 128 + cb;
#pragma unroll
        for (int n8 = 0; n8 < 4; n8++)
            *(float2*)(oh + n8 * 8) = make_float2(sigm(xx[i][2*n8])   * cS[i][2*n8],
                                                  sigm(xx[i][2*n8+1]) * cS[i][2*n8+1]);
    }
#undef GATHER
#undef ZACC
}

extern "C" void kernel_launch(void* const* d_in, const int* in_sizes, int n_in,
                              void* d_out, int out_size)
{
    const float* emb     = (const float*)d_in[0];
    const float* h_child = (const float*)d_in[1];
    const float* c_child = (const float*)d_in[2];
    const int*   n_type  = (const int*)  d_in[3];
    const float* W_iou   = (const float*)d_in[4];
    const float* U_iou   = (const float*)d_in[5];
    const float* b_iou   = (const float*)d_in[6];
    const float* W_f     = (const float*)d_in[7];
    const float* U_f     = (const float*)d_in[8];
    const float* b_f     = (const float*)d_in[9];
    const float* g_i  = (const float*)d_in[10];
    const float* b_i  = (const float*)d_in[11];
    const float* g_o  = (const float*)d_in[12];
    const float* b_o  = (const float*)d_in[13];
    const float* g_u  = (const float*)d_in[14];
    const float* b_u  = (const float*)d_in[15];
    const float* gn_f = (const float*)d_in[16];
    const float* bn_f = (const float*)d_in[17];
    const float* gn_c = (const float*)d_in[18];
    const float* bn_c = (const float*)d_in[19];
    float* out = (float*)d_out;

    int n = in_sizes[0] / 128;

    static int smem_set = 0;
    if (!smem_set) {
        cudaFuncSetAttribute(treelstm_mma,
                             cudaFuncAttributeMaxDynamicSharedMemorySize,
                             SMEM_BYTES);
        smem_set = 1;
    }

    treelstm_mma<<<n / 128, THREADS, SMEM_BYTES>>>(
        emb, h_child, c_child, n_type, W_iou, U_iou, b_iou, W_f, U_f, b_f,
        g_i, b_i, g_o, b_o, g_u, b_u, gn_f, bn_f, gn_c, bn_c, out, n);
}